// round 1
// baseline (speedup 1.0000x reference)
#include <cuda_runtime.h>
#include <cuda_bf16.h>
#include <cstdint>

// Problem constants
#define BATCH 2
#define SEQ 2048
#define DMODEL 768
#define NHEAD 12
#define HDIM 64
#define MROWS (BATCH * SEQ)          // 4096
#define BHEADS (BATCH * NHEAD)       // 24

// ---------------- scratch (no allocation allowed) ----------------
__device__ float g_q[BHEADS * SEQ * HDIM];    // [b*H+h][s][d]
__device__ float g_k[BHEADS * SEQ * HDIM];
__device__ float g_v[BHEADS * SEQ * HDIM];
__device__ float g_ctx[MROWS * DMODEL];       // [b*S+s][dmodel]

// =================================================================
// Generic fp32 GEMM: out[m][n] = sum_k A[m][k] * W[n][k] + bias[n]
// BM=BN=128, BK=8, 256 threads, 8x8 micro-tile per thread.
// split==1 : write head-split layout [(b*H+h)][s][d]
// split==0 : write plain [m][n]
// Assumes M%128==0, N%128==0, K%8==0 (true for all call sites).
// =================================================================
__global__ __launch_bounds__(256, 2)
void gemm_bias_kernel(const float* __restrict__ A, const float* __restrict__ W,
                      const float* __restrict__ bias, float* __restrict__ out,
                      int M, int N, int K, int split)
{
    __shared__ float As[8][128];   // [k][m]
    __shared__ float Bs[8][128];   // [k][n]

    const int tid = threadIdx.x;
    const int bm = blockIdx.x * 128;
    const int bn = blockIdx.y * 128;

    const int ty = tid >> 4;       // 0..15
    const int tx = tid & 15;       // 0..15
    const int r0 = ty * 8;
    const int c0 = tx * 8;

    // loader indices: each thread loads one float4 of A and one of W per k-step
    const int lr = tid >> 1;           // 0..127
    const int lc4 = (tid & 1) * 4;     // 0 or 4

    float acc[8][8];
#pragma unroll
    for (int i = 0; i < 8; i++)
#pragma unroll
        for (int j = 0; j < 8; j++) acc[i][j] = 0.f;

    for (int k0 = 0; k0 < K; k0 += 8) {
        // load A tile (transpose into [k][m])
        float4 a4 = *reinterpret_cast<const float4*>(&A[(size_t)(bm + lr) * K + k0 + lc4]);
        float4 b4 = *reinterpret_cast<const float4*>(&W[(size_t)(bn + lr) * K + k0 + lc4]);
        As[lc4 + 0][lr] = a4.x; As[lc4 + 1][lr] = a4.y;
        As[lc4 + 2][lr] = a4.z; As[lc4 + 3][lr] = a4.w;
        Bs[lc4 + 0][lr] = b4.x; Bs[lc4 + 1][lr] = b4.y;
        Bs[lc4 + 2][lr] = b4.z; Bs[lc4 + 3][lr] = b4.w;
        __syncthreads();

#pragma unroll
        for (int k = 0; k < 8; k++) {
            float4 af0 = *reinterpret_cast<const float4*>(&As[k][r0]);
            float4 af1 = *reinterpret_cast<const float4*>(&As[k][r0 + 4]);
            float4 bf0 = *reinterpret_cast<const float4*>(&Bs[k][c0]);
            float4 bf1 = *reinterpret_cast<const float4*>(&Bs[k][c0 + 4]);
            float af[8] = {af0.x, af0.y, af0.z, af0.w, af1.x, af1.y, af1.z, af1.w};
            float bf[8] = {bf0.x, bf0.y, bf0.z, bf0.w, bf1.x, bf1.y, bf1.z, bf1.w};
#pragma unroll
            for (int i = 0; i < 8; i++)
#pragma unroll
                for (int j = 0; j < 8; j++)
                    acc[i][j] = fmaf(af[i], bf[j], acc[i][j]);
        }
        __syncthreads();
    }

    // epilogue
#pragma unroll
    for (int i = 0; i < 8; i++) {
        const int m = bm + r0 + i;
#pragma unroll
        for (int j = 0; j < 8; j++) {
            const int n = bn + c0 + j;
            float val = acc[i][j] + bias[n];
            if (split) {
                const int b = m >> 11;          // m / SEQ
                const int s = m & (SEQ - 1);
                const int h = n >> 6;           // n / HDIM
                const int d = n & (HDIM - 1);
                out[(((size_t)(b * NHEAD + h) * SEQ) + s) * HDIM + d] = val;
            } else {
                out[(size_t)m * N + n] = val;
            }
        }
    }
}

// =================================================================
// Flash attention (causal), fp32.
// grid: (SEQ/64 q-tiles, BHEADS), 256 threads.
// Q/K/V layout: [bh][s][64]. Output written to g_ctx [b*S+s][768].
// =================================================================
#define QT 64
#define LDT 68   // padded stride (floats), keeps float4 alignment, shifts banks

__global__ __launch_bounds__(256, 2)
void attn_kernel(const float* __restrict__ Q, const float* __restrict__ K,
                 const float* __restrict__ V, float* __restrict__ ctx)
{
    extern __shared__ float sm[];
    float* Qt = sm;                      // [d][r]  64 x LDT
    float* Kt = Qt + QT * LDT;           // [d][c]
    float* Vs = Kt + QT * LDT;           // [j][c]
    float* Ss = Vs + QT * LDT;           // [r][c] raw scores
    float* Pt = Ss + QT * LDT;           // [c][r] exp probabilities
    float* mrow = Pt + QT * LDT;         // [64]
    float* lrow = mrow + QT;             // [64]
    float* arow = lrow + QT;             // [64]

    const int qt = blockIdx.x;           // 0..31
    const int bh = blockIdx.y;           // 0..23
    const int tid = threadIdx.x;

    const int ty = tid >> 4;             // 0..15
    const int tx = tid & 15;
    const int r0 = ty * 4;
    const int c0 = tx * 4;

    const float* Qp = Q + ((size_t)bh * SEQ + qt * QT) * HDIM;
    const float SCALE = 0.125f;          // 1/sqrt(64)

    // load Q tile transposed (pre-scaled)
#pragma unroll
    for (int i = 0; i < 4; i++) {
        int idx = tid + i * 256;         // 0..1023
        int r = idx >> 4;
        int d4 = (idx & 15) * 4;
        float4 q4 = *reinterpret_cast<const float4*>(&Qp[r * HDIM + d4]);
        Qt[(d4 + 0) * LDT + r] = q4.x * SCALE;
        Qt[(d4 + 1) * LDT + r] = q4.y * SCALE;
        Qt[(d4 + 2) * LDT + r] = q4.z * SCALE;
        Qt[(d4 + 3) * LDT + r] = q4.w * SCALE;
    }
    if (tid < QT) { mrow[tid] = -1e30f; lrow[tid] = 0.f; }

    float o[4][4];
#pragma unroll
    for (int i = 0; i < 4; i++)
#pragma unroll
        for (int j = 0; j < 4; j++) o[i][j] = 0.f;

    const int ntiles = qt + 1;           // causal
    for (int jt = 0; jt < ntiles; jt++) {
        __syncthreads();   // previous PV readers done; Qt ready on first iter

        const float* Kp = K + ((size_t)bh * SEQ + jt * QT) * HDIM;
        const float* Vp = V + ((size_t)bh * SEQ + jt * QT) * HDIM;
#pragma unroll
        for (int i = 0; i < 4; i++) {
            int idx = tid + i * 256;
            int r = idx >> 4;
            int d4 = (idx & 15) * 4;
            float4 k4 = *reinterpret_cast<const float4*>(&Kp[r * HDIM + d4]);
            Kt[(d4 + 0) * LDT + r] = k4.x;
            Kt[(d4 + 1) * LDT + r] = k4.y;
            Kt[(d4 + 2) * LDT + r] = k4.z;
            Kt[(d4 + 3) * LDT + r] = k4.w;
            float4 v4 = *reinterpret_cast<const float4*>(&Vp[r * HDIM + d4]);
            *reinterpret_cast<float4*>(&Vs[r * LDT + d4]) = v4;
        }
        __syncthreads();

        // S = Q * K^T  (4x4 per thread)
        float acc[4][4];
#pragma unroll
        for (int i = 0; i < 4; i++)
#pragma unroll
            for (int j = 0; j < 4; j++) acc[i][j] = 0.f;

#pragma unroll 4
        for (int d = 0; d < HDIM; d++) {
            float4 qa = *reinterpret_cast<const float4*>(&Qt[d * LDT + r0]);
            float4 kb = *reinterpret_cast<const float4*>(&Kt[d * LDT + c0]);
            float qf[4] = {qa.x, qa.y, qa.z, qa.w};
            float kf[4] = {kb.x, kb.y, kb.z, kb.w};
#pragma unroll
            for (int i = 0; i < 4; i++)
#pragma unroll
                for (int j = 0; j < 4; j++)
                    acc[i][j] = fmaf(qf[i], kf[j], acc[i][j]);
        }

        // causal mask + spill raw scores
        const int qbase = qt * QT, kbase = jt * QT;
#pragma unroll
        for (int i = 0; i < 4; i++) {
            const int gr = qbase + r0 + i;
#pragma unroll
            for (int j = 0; j < 4; j++) {
                const int gc = kbase + c0 + j;
                Ss[(r0 + i) * LDT + c0 + j] = (gc <= gr) ? acc[i][j] : -1e30f;
            }
        }
        __syncthreads();

        // online softmax: one thread per row
        if (tid < QT) {
            const int r = tid;
            float mo = mrow[r];
            float mx = mo;
#pragma unroll 8
            for (int c = 0; c < QT; c++) mx = fmaxf(mx, Ss[r * LDT + c]);
            float alpha = __expf(mo - mx);
            float lsum = 0.f;
#pragma unroll 8
            for (int c = 0; c < QT; c++) {
                float p = __expf(Ss[r * LDT + c] - mx);
                Pt[c * LDT + r] = p;
                lsum += p;
            }
            mrow[r] = mx;
            lrow[r] = alpha * lrow[r] + lsum;
            arow[r] = alpha;
        }
        __syncthreads();

        // rescale O, then O += P * V
        float ai[4];
#pragma unroll
        for (int i = 0; i < 4; i++) ai[i] = arow[r0 + i];
#pragma unroll
        for (int i = 0; i < 4; i++)
#pragma unroll
            for (int j = 0; j < 4; j++) o[i][j] *= ai[i];

#pragma unroll 4
        for (int j64 = 0; j64 < QT; j64++) {
            float4 pa = *reinterpret_cast<const float4*>(&Pt[j64 * LDT + r0]);
            float4 vb = *reinterpret_cast<const float4*>(&Vs[j64 * LDT + c0]);
            float pf[4] = {pa.x, pa.y, pa.z, pa.w};
            float vf[4] = {vb.x, vb.y, vb.z, vb.w};
#pragma unroll
            for (int i = 0; i < 4; i++)
#pragma unroll
                for (int j = 0; j < 4; j++)
                    o[i][j] = fmaf(pf[i], vf[j], o[i][j]);
        }
    }

    // epilogue: normalize and write to ctx [b*S+s][768]
    float linv[4];
#pragma unroll
    for (int i = 0; i < 4; i++) linv[i] = 1.f / lrow[r0 + i];

    const int b = bh / NHEAD;
    const int h = bh % NHEAD;
#pragma unroll
    for (int i = 0; i < 4; i++) {
        const int s = qt * QT + r0 + i;
        float* dst = ctx + ((size_t)(b * SEQ + s)) * DMODEL + h * HDIM + c0;
#pragma unroll
        for (int j = 0; j < 4; j++) dst[j] = o[i][j] * linv[i];
    }
}

// =================================================================
// launcher
// =================================================================
extern "C" void kernel_launch(void* const* d_in, const int* in_sizes, int n_in,
                              void* d_out, int out_size)
{
    (void)in_sizes; (void)n_in; (void)out_size;
    const float* query = (const float*)d_in[0];
    const float* key   = (const float*)d_in[1];
    const float* value = (const float*)d_in[2];
    // d_in[3] is the mask: known tril(ones) — causality applied analytically
    const float* Wq = (const float*)d_in[4];
    const float* bq = (const float*)d_in[5];
    const float* Wk = (const float*)d_in[6];
    const float* bk = (const float*)d_in[7];
    const float* Wv = (const float*)d_in[8];
    const float* bv = (const float*)d_in[9];
    const float* Wo = (const float*)d_in[10];
    const float* bo = (const float*)d_in[11];
    float* out = (float*)d_out;

    float *qp, *kp, *vp, *cp;
    cudaGetSymbolAddress((void**)&qp, g_q);
    cudaGetSymbolAddress((void**)&kp, g_k);
    cudaGetSymbolAddress((void**)&vp, g_v);
    cudaGetSymbolAddress((void**)&cp, g_ctx);

    dim3 gproj(MROWS / 128, DMODEL / 128);   // (32, 6)
    gemm_bias_kernel<<<gproj, 256>>>(query, Wq, bq, qp, MROWS, DMODEL, DMODEL, 1);
    gemm_bias_kernel<<<gproj, 256>>>(key,   Wk, bk, kp, MROWS, DMODEL, DMODEL, 1);
    gemm_bias_kernel<<<gproj, 256>>>(value, Wv, bv, vp, MROWS, DMODEL, DMODEL, 1);

    const int smem = (5 * QT * LDT + 3 * QT) * sizeof(float);  // 87,808 B
    cudaFuncSetAttribute(attn_kernel, cudaFuncAttributeMaxDynamicSharedMemorySize, smem);
    dim3 gattn(SEQ / QT, BHEADS);            // (32, 24)
    attn_kernel<<<gattn, 256, smem>>>(qp, kp, vp, cp);

    gemm_bias_kernel<<<gproj, 256>>>(cp, Wo, bo, out, MROWS, DMODEL, DMODEL, 0);
}

// round 2
// speedup vs baseline: 2.8534x; 2.8534x over previous
#include <cuda_runtime.h>
#include <cuda_bf16.h>
#include <cstdint>

#define BATCH 2
#define SEQ 2048
#define DMODEL 768
#define NHEAD 12
#define HDIM 64
#define MROWS (BATCH * SEQ)          // 4096
#define BHEADS (BATCH * NHEAD)       // 24

// ---------------- scratch ----------------
__device__ float g_q[BHEADS * SEQ * HDIM];
__device__ float g_k[BHEADS * SEQ * HDIM];
__device__ float g_v[BHEADS * SEQ * HDIM];
__device__ float g_ctx[MROWS * DMODEL];

__device__ __forceinline__ uint32_t f2tf(float f) {
    uint32_t r; asm("cvt.rna.tf32.f32 %0, %1;" : "=r"(r) : "f"(f)); return r;
}

__device__ __forceinline__ void mma_tf32(float c[4], const uint32_t a[4], const uint32_t b[2]) {
    asm volatile(
        "mma.sync.aligned.m16n8k8.row.col.f32.tf32.tf32.f32 "
        "{%0,%1,%2,%3}, {%4,%5,%6,%7}, {%8,%9}, {%0,%1,%2,%3};"
        : "+f"(c[0]), "+f"(c[1]), "+f"(c[2]), "+f"(c[3])
        : "r"(a[0]), "r"(a[1]), "r"(a[2]), "r"(a[3]), "r"(b[0]), "r"(b[1]));
}

// =================================================================
// tf32 GEMM: out[m][n] = A[m][:] . W[n][:] + bias[n]
// BM=128 BN=128 BK=16, 256 threads, warp tile 64x32.
// =================================================================
#define PITCH 20
__global__ __launch_bounds__(256)
void gemm_tf32(const float* __restrict__ A, const float* __restrict__ W,
               const float* __restrict__ bias, float* __restrict__ out,
               int M, int N, int K, int split)
{
    __shared__ uint32_t As[2][128 * PITCH];
    __shared__ uint32_t Bs[2][128 * PITCH];

    const int tid = threadIdx.x;
    const int wid = tid >> 5, lane = tid & 31;
    const int gid = lane >> 2, l4 = lane & 3;
    const int bm = blockIdx.x * 128;
    const int bn = blockIdx.y * 128;
    const int wm = (wid & 1) * 64;
    const int wn = (wid >> 1) * 32;

    // staging: thread loads 2 float4 of A and 2 of W per BK=16
    const int srow = tid >> 1;
    const int scol = (tid & 1) * 8;
    const float* Ag = A + (size_t)(bm + srow) * K + scol;
    const float* Wg = W + (size_t)(bn + srow) * K + scol;

    float acc[4][4][4];
#pragma unroll
    for (int i = 0; i < 4; i++)
#pragma unroll
        for (int j = 0; j < 4; j++)
#pragma unroll
            for (int t = 0; t < 4; t++) acc[i][j][t] = 0.f;

    // prologue loads
    float4 ra0 = *reinterpret_cast<const float4*>(Ag);
    float4 ra1 = *reinterpret_cast<const float4*>(Ag + 4);
    float4 rb0 = *reinterpret_cast<const float4*>(Wg);
    float4 rb1 = *reinterpret_cast<const float4*>(Wg + 4);

    const int nIter = K / 16;
    for (int it = 0; it < nIter; it++) {
        const int buf = it & 1;
        // store staged tile (tf32-converted)
        uint32_t* as = &As[buf][srow * PITCH + scol];
        uint32_t* bs = &Bs[buf][srow * PITCH + scol];
        as[0] = f2tf(ra0.x); as[1] = f2tf(ra0.y); as[2] = f2tf(ra0.z); as[3] = f2tf(ra0.w);
        as[4] = f2tf(ra1.x); as[5] = f2tf(ra1.y); as[6] = f2tf(ra1.z); as[7] = f2tf(ra1.w);
        bs[0] = f2tf(rb0.x); bs[1] = f2tf(rb0.y); bs[2] = f2tf(rb0.z); bs[3] = f2tf(rb0.w);
        bs[4] = f2tf(rb1.x); bs[5] = f2tf(rb1.y); bs[6] = f2tf(rb1.z); bs[7] = f2tf(rb1.w);
        __syncthreads();

        if (it + 1 < nIter) {
            Ag += 16; Wg += 16;
            ra0 = *reinterpret_cast<const float4*>(Ag);
            ra1 = *reinterpret_cast<const float4*>(Ag + 4);
            rb0 = *reinterpret_cast<const float4*>(Wg);
            rb1 = *reinterpret_cast<const float4*>(Wg + 4);
        }

#pragma unroll
        for (int kk = 0; kk < 16; kk += 8) {
            uint32_t af[4][4], bf[4][2];
#pragma unroll
            for (int mt = 0; mt < 4; mt++) {
                const int base = (wm + mt * 16 + gid) * PITCH + kk + l4;
                af[mt][0] = As[buf][base];
                af[mt][1] = As[buf][base + 8 * PITCH];
                af[mt][2] = As[buf][base + 4];
                af[mt][3] = As[buf][base + 8 * PITCH + 4];
            }
#pragma unroll
            for (int nt = 0; nt < 4; nt++) {
                const int base = (wn + nt * 8 + gid) * PITCH + kk + l4;
                bf[nt][0] = Bs[buf][base];
                bf[nt][1] = Bs[buf][base + 4];
            }
#pragma unroll
            for (int mt = 0; mt < 4; mt++)
#pragma unroll
                for (int nt = 0; nt < 4; nt++)
                    mma_tf32(acc[mt][nt], af[mt], bf[nt]);
        }
        __syncthreads();
    }

    // epilogue
#pragma unroll
    for (int mt = 0; mt < 4; mt++) {
#pragma unroll
        for (int nt = 0; nt < 4; nt++) {
#pragma unroll
            for (int half = 0; half < 2; half++) {      // c0,c1 (row gid) / c2,c3 (row gid+8)
                const int m = bm + wm + mt * 16 + gid + half * 8;
#pragma unroll
                for (int t = 0; t < 2; t++) {
                    const int n = bn + wn + nt * 8 + 2 * l4 + t;
                    float val = acc[mt][nt][half * 2 + t] + bias[n];
                    if (split) {
                        const int b = m >> 11;
                        const int s = m & (SEQ - 1);
                        const int h = n >> 6;
                        const int d = n & (HDIM - 1);
                        out[(((size_t)(b * NHEAD + h) * SEQ) + s) * HDIM + d] = val;
                    } else {
                        out[(size_t)m * N + n] = val;
                    }
                }
            }
        }
    }
}

// =================================================================
// Flash attention (causal), tf32 mma. 128 threads (4 warps).
// Q tile 64x64 held in registers as A-fragments; K/V/P staged in smem.
// =================================================================
#define KPITCH 68   // [n][k] and [m][k] layouts
#define VPITCH 72   // [k][d] layout

__global__ __launch_bounds__(128)
void attn_tf32(const float* __restrict__ Q, const float* __restrict__ K,
               const float* __restrict__ V, float* __restrict__ ctx)
{
    extern __shared__ uint32_t smu[];
    uint32_t* Ks = smu;                    // 64*68
    uint32_t* Vs = Ks + 64 * KPITCH;       // 64*72
    uint32_t* Ps = Vs + 64 * VPITCH;       // 64*68 (also Q staging)

    const int tid = threadIdx.x;
    const int w = tid >> 5, lane = tid & 31;
    const int gid = lane >> 2, l4 = lane & 3;
    const int qt = blockIdx.x;
    const int bh = blockIdx.y;

    const float* Qp = Q + ((size_t)bh * SEQ + qt * 64) * HDIM;
    const float SCALE = 0.125f;

    // stage Q (scaled, tf32) into Ps
#pragma unroll
    for (int i = 0; i < 8; i++) {
        int idx = i * 128 + tid;           // 0..1023 float4s
        int r = idx >> 4;
        int c4 = (idx & 15) << 2;
        float4 q4 = *reinterpret_cast<const float4*>(&Qp[r * HDIM + c4]);
        uint32_t* dst = &Ps[r * KPITCH + c4];
        dst[0] = f2tf(q4.x * SCALE); dst[1] = f2tf(q4.y * SCALE);
        dst[2] = f2tf(q4.z * SCALE); dst[3] = f2tf(q4.w * SCALE);
    }
    __syncthreads();

    // load Q fragments (warp's 16 rows, all 64 k)
    uint32_t qf[8][4];
    const int m0 = w * 16;
#pragma unroll
    for (int kt = 0; kt < 8; kt++) {
        const int base = (m0 + gid) * KPITCH + kt * 8 + l4;
        qf[kt][0] = Ps[base];
        qf[kt][1] = Ps[base + 8 * KPITCH];
        qf[kt][2] = Ps[base + 4];
        qf[kt][3] = Ps[base + 8 * KPITCH + 4];
    }
    // NOTE: no sync needed here; the staging sync inside the first loop
    // iteration orders these LDS before any Ps overwrite.

    float o[8][4];
#pragma unroll
    for (int dt = 0; dt < 8; dt++)
#pragma unroll
        for (int t = 0; t < 4; t++) o[dt][t] = 0.f;

    float m_a = -1e30f, m_b = -1e30f;
    float l_a = 0.f, l_b = 0.f;

    const int ntiles = qt + 1;
    for (int jt = 0; jt < ntiles; jt++) {
        // stage K tile [n][k] and V tile [k][d]
        const float* Kp = K + ((size_t)bh * SEQ + jt * 64) * HDIM;
        const float* Vp = V + ((size_t)bh * SEQ + jt * 64) * HDIM;
#pragma unroll
        for (int i = 0; i < 8; i++) {
            int idx = i * 128 + tid;
            int r = idx >> 4;
            int c4 = (idx & 15) << 2;
            float4 k4 = *reinterpret_cast<const float4*>(&Kp[r * HDIM + c4]);
            uint32_t* kd = &Ks[r * KPITCH + c4];
            kd[0] = f2tf(k4.x); kd[1] = f2tf(k4.y); kd[2] = f2tf(k4.z); kd[3] = f2tf(k4.w);
            float4 v4 = *reinterpret_cast<const float4*>(&Vp[r * HDIM + c4]);
            uint32_t* vd = &Vs[r * VPITCH + c4];
            vd[0] = f2tf(v4.x); vd[1] = f2tf(v4.y); vd[2] = f2tf(v4.z); vd[3] = f2tf(v4.w);
        }
        __syncthreads();

        // S = Q K^T : warp rows m0..m0+15, cols 0..63
        float s[8][4];
#pragma unroll
        for (int nt = 0; nt < 8; nt++)
#pragma unroll
            for (int t = 0; t < 4; t++) s[nt][t] = 0.f;

#pragma unroll
        for (int kt = 0; kt < 8; kt++) {
#pragma unroll
            for (int nt = 0; nt < 8; nt++) {
                uint32_t bfr[2];
                const int base = (nt * 8 + gid) * KPITCH + kt * 8 + l4;
                bfr[0] = Ks[base];
                bfr[1] = Ks[base + 4];
                mma_tf32(s[nt], qf[kt], bfr);
            }
        }

        // causal mask on diagonal tile only
        if (jt == qt) {
            const int ra = m0 + gid, rb = ra + 8;
#pragma unroll
            for (int nt = 0; nt < 8; nt++) {
                const int c = nt * 8 + 2 * l4;
                if (c > ra)     s[nt][0] = -1e30f;
                if (c + 1 > ra) s[nt][1] = -1e30f;
                if (c > rb)     s[nt][2] = -1e30f;
                if (c + 1 > rb) s[nt][3] = -1e30f;
            }
        }

        // online softmax (rows a=gid, b=gid+8 of this warp's tile)
        float mxa = -1e30f, mxb = -1e30f;
#pragma unroll
        for (int nt = 0; nt < 8; nt++) {
            mxa = fmaxf(mxa, fmaxf(s[nt][0], s[nt][1]));
            mxb = fmaxf(mxb, fmaxf(s[nt][2], s[nt][3]));
        }
        mxa = fmaxf(mxa, __shfl_xor_sync(0xffffffffu, mxa, 1));
        mxa = fmaxf(mxa, __shfl_xor_sync(0xffffffffu, mxa, 2));
        mxb = fmaxf(mxb, __shfl_xor_sync(0xffffffffu, mxb, 1));
        mxb = fmaxf(mxb, __shfl_xor_sync(0xffffffffu, mxb, 2));

        const float mna = fmaxf(m_a, mxa);
        const float mnb = fmaxf(m_b, mxb);
        const float alpha_a = __expf(m_a - mna);
        const float alpha_b = __expf(m_b - mnb);
        m_a = mna; m_b = mnb;

        float suma = 0.f, sumb = 0.f;
        const int rowa = (m0 + gid) * KPITCH;
        const int rowb = (m0 + gid + 8) * KPITCH;
#pragma unroll
        for (int nt = 0; nt < 8; nt++) {
            const int c = nt * 8 + 2 * l4;
            float p0 = __expf(s[nt][0] - mna);
            float p1 = __expf(s[nt][1] - mna);
            float p2 = __expf(s[nt][2] - mnb);
            float p3 = __expf(s[nt][3] - mnb);
            suma += p0 + p1;
            sumb += p2 + p3;
            Ps[rowa + c] = f2tf(p0); Ps[rowa + c + 1] = f2tf(p1);
            Ps[rowb + c] = f2tf(p2); Ps[rowb + c + 1] = f2tf(p3);
        }
        l_a = l_a * alpha_a + suma;
        l_b = l_b * alpha_b + sumb;

        // rescale O
#pragma unroll
        for (int dt = 0; dt < 8; dt++) {
            o[dt][0] *= alpha_a; o[dt][1] *= alpha_a;
            o[dt][2] *= alpha_b; o[dt][3] *= alpha_b;
        }
        __syncthreads();   // Ps visible to own warp frags; also keeps tiles coherent

        // O += P V
#pragma unroll
        for (int kt = 0; kt < 8; kt++) {
            uint32_t pf[4];
            const int base = (m0 + gid) * KPITCH + kt * 8 + l4;
            pf[0] = Ps[base];
            pf[1] = Ps[base + 8 * KPITCH];
            pf[2] = Ps[base + 4];
            pf[3] = Ps[base + 8 * KPITCH + 4];
#pragma unroll
            for (int dt = 0; dt < 8; dt++) {
                uint32_t bfr[2];
                const int vb = (kt * 8 + l4) * VPITCH + dt * 8 + gid;
                bfr[0] = Vs[vb];
                bfr[1] = Vs[vb + 4 * VPITCH];
                mma_tf32(o[dt], pf, bfr);
            }
        }
        __syncthreads();   // all reads of Ks/Vs/Ps done before next staging
    }

    // finalize: quad-reduce l, normalize, write ctx
    l_a += __shfl_xor_sync(0xffffffffu, l_a, 1);
    l_a += __shfl_xor_sync(0xffffffffu, l_a, 2);
    l_b += __shfl_xor_sync(0xffffffffu, l_b, 1);
    l_b += __shfl_xor_sync(0xffffffffu, l_b, 2);
    const float ia = 1.f / l_a, ib = 1.f / l_b;

    const int b = bh / NHEAD;
    const int h = bh % NHEAD;
    const int sa = qt * 64 + m0 + gid;
    const int sb = sa + 8;
    float* da = ctx + ((size_t)(b * SEQ + sa)) * DMODEL + h * HDIM;
    float* db = ctx + ((size_t)(b * SEQ + sb)) * DMODEL + h * HDIM;
#pragma unroll
    for (int dt = 0; dt < 8; dt++) {
        const int c = dt * 8 + 2 * l4;
        da[c]     = o[dt][0] * ia;
        da[c + 1] = o[dt][1] * ia;
        db[c]     = o[dt][2] * ib;
        db[c + 1] = o[dt][3] * ib;
    }
}

// =================================================================
extern "C" void kernel_launch(void* const* d_in, const int* in_sizes, int n_in,
                              void* d_out, int out_size)
{
    (void)in_sizes; (void)n_in; (void)out_size;
    const float* query = (const float*)d_in[0];
    const float* key   = (const float*)d_in[1];
    const float* value = (const float*)d_in[2];
    const float* Wq = (const float*)d_in[4];
    const float* bq = (const float*)d_in[5];
    const float* Wk = (const float*)d_in[6];
    const float* bk = (const float*)d_in[7];
    const float* Wv = (const float*)d_in[8];
    const float* bv = (const float*)d_in[9];
    const float* Wo = (const float*)d_in[10];
    const float* bo = (const float*)d_in[11];
    float* out = (float*)d_out;

    float *qp, *kp, *vp, *cp;
    cudaGetSymbolAddress((void**)&qp, g_q);
    cudaGetSymbolAddress((void**)&kp, g_k);
    cudaGetSymbolAddress((void**)&vp, g_v);
    cudaGetSymbolAddress((void**)&cp, g_ctx);

    dim3 gproj(MROWS / 128, DMODEL / 128);   // (32, 6)
    gemm_tf32<<<gproj, 256>>>(query, Wq, bq, qp, MROWS, DMODEL, DMODEL, 1);
    gemm_tf32<<<gproj, 256>>>(key,   Wk, bk, kp, MROWS, DMODEL, DMODEL, 1);
    gemm_tf32<<<gproj, 256>>>(value, Wv, bv, vp, MROWS, DMODEL, DMODEL, 1);

    const int smem = (64 * KPITCH + 64 * VPITCH + 64 * KPITCH) * 4;  // 53,248 B
    static bool attr_set = false;
    if (!attr_set) {
        cudaFuncSetAttribute(attn_tf32, cudaFuncAttributeMaxDynamicSharedMemorySize, smem);
        attr_set = true;
    }
    dim3 gattn(SEQ / 64, BHEADS);            // (32, 24)
    attn_tf32<<<gattn, 128, smem>>>(qp, kp, vp, cp);

    gemm_tf32<<<gproj, 256>>>(cp, Wo, bo, out, MROWS, DMODEL, DMODEL, 0);
}

// round 3
// speedup vs baseline: 3.7212x; 1.3041x over previous
#include <cuda_runtime.h>
#include <cuda_bf16.h>
#include <cstdint>

#define BATCH 2
#define SEQ 2048
#define DMODEL 768
#define NHEAD 12
#define HDIM 64
#define MROWS (BATCH * SEQ)          // 4096
#define BHEADS (BATCH * NHEAD)       // 24

// ---------------- scratch ----------------
__device__ uint32_t g_q[BHEADS * SEQ * HDIM];   // tf32 bits, pre-scaled
__device__ uint32_t g_k[BHEADS * SEQ * HDIM];   // tf32 bits
__device__ uint32_t g_v[BHEADS * SEQ * HDIM];   // tf32 bits
__device__ float    g_ctx[MROWS * DMODEL];

__device__ __forceinline__ uint32_t f2tf(float f) {
    uint32_t r; asm("cvt.rna.tf32.f32 %0, %1;" : "=r"(r) : "f"(f)); return r;
}

__device__ __forceinline__ void mma_tf32(float c[4], const uint32_t a[4], const uint32_t b[2]) {
    asm volatile(
        "mma.sync.aligned.m16n8k8.row.col.f32.tf32.tf32.f32 "
        "{%0,%1,%2,%3}, {%4,%5,%6,%7}, {%8,%9}, {%0,%1,%2,%3};"
        : "+f"(c[0]), "+f"(c[1]), "+f"(c[2]), "+f"(c[3])
        : "r"(a[0]), "r"(a[1]), "r"(a[2]), "r"(a[3]), "r"(b[0]), "r"(b[1]));
}

__device__ __forceinline__ void cp16(uint32_t s, const void* g) {
    asm volatile("cp.async.cg.shared.global [%0], [%1], 16;" :: "r"(s), "l"(g));
}
__device__ __forceinline__ void cp_commit() {
    asm volatile("cp.async.commit_group;");
}
__device__ __forceinline__ void cp_wait0() {
    asm volatile("cp.async.wait_group 0;");
}

// =================================================================
// Fused GEMM: out[m][n] = A[m][:] . W[n][:] + bias[n]
// CTA tile 128x64, BK=16, 128 threads (4 warps), warp tile 64x32.
// z-indexed operand sets. split: write tf32 head-split layout.
// =================================================================
struct GemmArgs {
    const float* A[3];
    const float* W[3];
    const float* bias[3];
    void*        out[3];
    float        scale[3];
    int          split[3];
};

#define GP 20
__global__ __launch_bounds__(128, 3)
void gemm_fused(GemmArgs args)
{
    __shared__ uint32_t As[2][128 * GP];
    __shared__ uint32_t Bs[2][64 * GP];

    const int z = blockIdx.z;
    const float* __restrict__ A    = args.A[z];
    const float* __restrict__ W    = args.W[z];
    const float* __restrict__ bias = args.bias[z];
    const float scale = args.scale[z];
    const int   split = args.split[z];

    const int tid = threadIdx.x;
    const int w = tid >> 5, lane = tid & 31;
    const int gid = lane >> 2, l4 = lane & 3;
    const int bm = blockIdx.x * 128;
    const int bn = blockIdx.y * 64;
    const int wm = (w & 1) * 64;
    const int wn = (w >> 1) * 32;

    // coalesced staging: 4 threads per row (16B each)
    const int arow = tid >> 2;           // A rows handled: arow, +32, +64, +96
    const int kq4  = (tid & 3) * 4;      // k offset within BK
    const float* Ag = A + (size_t)(bm + arow) * DMODEL + kq4;
    const float* Wg = W + (size_t)(bn + arow) * DMODEL + kq4;  // B rows: arow, arow+32

    float acc[4][4][4];
#pragma unroll
    for (int i = 0; i < 4; i++)
#pragma unroll
        for (int j = 0; j < 4; j++)
#pragma unroll
            for (int t = 0; t < 4; t++) acc[i][j][t] = 0.f;

    float4 ra[4], rb[2];
#define LOADREGS(K0) do { \
    ra[0] = *reinterpret_cast<const float4*>(Ag + (K0)); \
    ra[1] = *reinterpret_cast<const float4*>(Ag + (K0) + (size_t)32 * DMODEL); \
    ra[2] = *reinterpret_cast<const float4*>(Ag + (K0) + (size_t)64 * DMODEL); \
    ra[3] = *reinterpret_cast<const float4*>(Ag + (K0) + (size_t)96 * DMODEL); \
    rb[0] = *reinterpret_cast<const float4*>(Wg + (K0)); \
    rb[1] = *reinterpret_cast<const float4*>(Wg + (K0) + (size_t)32 * DMODEL); \
} while (0)

#define STORESTAGE(B) do { \
    uint32_t* asym; uint4 u; \
    _Pragma("unroll") \
    for (int i = 0; i < 4; i++) { \
        asym = &As[B][(arow + i * 32) * GP + kq4]; \
        u.x = f2tf(ra[i].x); u.y = f2tf(ra[i].y); u.z = f2tf(ra[i].z); u.w = f2tf(ra[i].w); \
        *reinterpret_cast<uint4*>(asym) = u; \
    } \
    _Pragma("unroll") \
    for (int i = 0; i < 2; i++) { \
        asym = &Bs[B][(arow + i * 32) * GP + kq4]; \
        u.x = f2tf(rb[i].x); u.y = f2tf(rb[i].y); u.z = f2tf(rb[i].z); u.w = f2tf(rb[i].w); \
        *reinterpret_cast<uint4*>(asym) = u; \
    } \
} while (0)

    const int nIter = DMODEL / 16;       // 48
    LOADREGS(0);
    STORESTAGE(0);
    LOADREGS(16);
    __syncthreads();

    for (int it = 0; it < nIter; it++) {
        const int buf = it & 1;
        if (it + 1 < nIter) STORESTAGE(buf ^ 1);
        if (it + 2 < nIter) LOADREGS((it + 2) * 16);

#pragma unroll
        for (int kk = 0; kk < 16; kk += 8) {
            uint32_t af[4][4], bf[4][2];
#pragma unroll
            for (int mt = 0; mt < 4; mt++) {
                const int base = (wm + mt * 16 + gid) * GP + kk + l4;
                af[mt][0] = As[buf][base];
                af[mt][1] = As[buf][base + 8 * GP];
                af[mt][2] = As[buf][base + 4];
                af[mt][3] = As[buf][base + 8 * GP + 4];
            }
#pragma unroll
            for (int nt = 0; nt < 4; nt++) {
                const int bb = (wn + nt * 8 + gid) * GP + kk + l4;
                bf[nt][0] = Bs[buf][bb];
                bf[nt][1] = Bs[buf][bb + 4];
            }
#pragma unroll
            for (int mt = 0; mt < 4; mt++)
#pragma unroll
                for (int nt = 0; nt < 4; nt++)
                    mma_tf32(acc[mt][nt], af[mt], bf[nt]);
        }
        __syncthreads();
    }

    // epilogue
#pragma unroll
    for (int mt = 0; mt < 4; mt++) {
#pragma unroll
        for (int nt = 0; nt < 4; nt++) {
#pragma unroll
            for (int half = 0; half < 2; half++) {
                const int m = bm + wm + mt * 16 + gid + half * 8;
#pragma unroll
                for (int t = 0; t < 2; t++) {
                    const int n = bn + wn + nt * 8 + 2 * l4 + t;
                    float val = (acc[mt][nt][half * 2 + t] + bias[n]) * scale;
                    if (split) {
                        const int b = m >> 11;
                        const int s = m & (SEQ - 1);
                        const int h = n >> 6;
                        const int d = n & (HDIM - 1);
                        ((uint32_t*)args.out[z])[(((size_t)(b * NHEAD + h) * SEQ) + s) * HDIM + d] = f2tf(val);
                    } else {
                        ((float*)args.out[z])[(size_t)m * DMODEL + n] = val;
                    }
                }
            }
        }
    }
}

// =================================================================
// Flash attention (causal), tf32. 128 threads (4 warps), q-tile 64.
// Inputs pre-converted tf32 (Q pre-scaled). Double-buffered K/V via
// cp.async; one barrier per KV tile; P exchanged via quad shuffles.
// =================================================================
#define KPITCH 68
#define VPITCH 72
#define KWORDS (64 * KPITCH)   // 4352
#define VWORDS (64 * VPITCH)   // 4608
#define ATTN_SMEM ((2 * KWORDS + 2 * VWORDS) * 4)   // 71680 B

__global__ __launch_bounds__(128, 3)
void attn_tf32(const uint32_t* __restrict__ Q, const uint32_t* __restrict__ K,
               const uint32_t* __restrict__ V, float* __restrict__ ctx)
{
    extern __shared__ uint32_t smu[];
    // layout: Ks[0], Ks[1], Vs[0], Vs[1]
    uint32_t* KsBuf[2] = { smu, smu + KWORDS };
    uint32_t* VsBuf[2] = { smu + 2 * KWORDS, smu + 2 * KWORDS + VWORDS };
    const uint32_t smem_u32 = (uint32_t)__cvta_generic_to_shared(smu);

    const int tid = threadIdx.x;
    const int w = tid >> 5, lane = tid & 31;
    const int gid = lane >> 2, l4 = lane & 3;
    const int qt = blockIdx.x;
    const int bh = blockIdx.y;
    const int m0 = w * 16;

    const uint32_t* Kbase = K + ((size_t)bh * SEQ) * HDIM;
    const uint32_t* Vbase = V + ((size_t)bh * SEQ) * HDIM;

    // ---- stage helper: copy 64x64 K and V tiles (pure cp.async) ----
    auto stage = [&](int jt, int buf) {
        const char* Kg = (const char*)(Kbase + (size_t)jt * 64 * HDIM);
        const char* Vg = (const char*)(Vbase + (size_t)jt * 64 * HDIM);
        const uint32_t ksb = smem_u32 + (buf ? KWORDS * 4 : 0);
        const uint32_t vsb = smem_u32 + (2 * KWORDS + (buf ? VWORDS : 0)) * 4;
#pragma unroll
        for (int i = 0; i < 8; i++) {
            const int idx = i * 128 + tid;     // 0..1023 float4s
            const int r = idx >> 4;
            const int c4 = (idx & 15) << 2;
            cp16(ksb + (r * KPITCH + c4) * 4, Kg + idx * 16);
            cp16(vsb + (r * VPITCH + c4) * 4, Vg + idx * 16);
        }
        cp_commit();
    };

    // ---- load Q fragments directly from global (one-time) ----
    uint32_t qf[8][4];
    {
        const uint32_t* Qg = Q + ((size_t)bh * SEQ + qt * 64) * HDIM;
#pragma unroll
        for (int kt = 0; kt < 8; kt++) {
            const int base = (m0 + gid) * HDIM + kt * 8 + l4;
            qf[kt][0] = Qg[base];
            qf[kt][1] = Qg[base + 8 * HDIM];
            qf[kt][2] = Qg[base + 4];
            qf[kt][3] = Qg[base + 8 * HDIM + 4];
        }
    }

    stage(0, 0);
    cp_wait0();
    __syncthreads();

    float o[8][4];
#pragma unroll
    for (int dt = 0; dt < 8; dt++)
#pragma unroll
        for (int t = 0; t < 4; t++) o[dt][t] = 0.f;

    float m_a = -1e30f, m_b = -1e30f;
    float l_a = 0.f, l_b = 0.f;

    const int ntiles = qt + 1;
    for (int jt = 0; jt < ntiles; jt++) {
        const int buf = jt & 1;
        if (jt + 1 < ntiles) stage(jt + 1, buf ^ 1);

        const uint32_t* Ks = KsBuf[buf];
        const uint32_t* Vs = VsBuf[buf];

        // ---- S = Q K^T ----
        float s[8][4];
#pragma unroll
        for (int nt = 0; nt < 8; nt++)
#pragma unroll
            for (int t = 0; t < 4; t++) s[nt][t] = 0.f;

#pragma unroll
        for (int kt = 0; kt < 8; kt++) {
#pragma unroll
            for (int nt = 0; nt < 8; nt++) {
                uint32_t bfr[2];
                const int base = (nt * 8 + gid) * KPITCH + kt * 8 + l4;
                bfr[0] = Ks[base];
                bfr[1] = Ks[base + 4];
                mma_tf32(s[nt], qf[kt], bfr);
            }
        }

        // ---- causal mask on diagonal tile ----
        if (jt == qt) {
            const int ra = m0 + gid, rb = ra + 8;
#pragma unroll
            for (int nt = 0; nt < 8; nt++) {
                const int c = nt * 8 + 2 * l4;
                if (c > ra)     s[nt][0] = -1e30f;
                if (c + 1 > ra) s[nt][1] = -1e30f;
                if (c > rb)     s[nt][2] = -1e30f;
                if (c + 1 > rb) s[nt][3] = -1e30f;
            }
        }

        // ---- online softmax (rows gid, gid+8) ----
        float mxa = -1e30f, mxb = -1e30f;
#pragma unroll
        for (int nt = 0; nt < 8; nt++) {
            mxa = fmaxf(mxa, fmaxf(s[nt][0], s[nt][1]));
            mxb = fmaxf(mxb, fmaxf(s[nt][2], s[nt][3]));
        }
        mxa = fmaxf(mxa, __shfl_xor_sync(0xffffffffu, mxa, 1));
        mxa = fmaxf(mxa, __shfl_xor_sync(0xffffffffu, mxa, 2));
        mxb = fmaxf(mxb, __shfl_xor_sync(0xffffffffu, mxb, 1));
        mxb = fmaxf(mxb, __shfl_xor_sync(0xffffffffu, mxb, 2));

        const float mna = fmaxf(m_a, mxa);
        const float mnb = fmaxf(m_b, mxb);
        const float alpha_a = __expf(m_a - mna);
        const float alpha_b = __expf(m_b - mnb);
        m_a = mna; m_b = mnb;

        float suma = 0.f, sumb = 0.f;
#pragma unroll
        for (int nt = 0; nt < 8; nt++) {
            s[nt][0] = __expf(s[nt][0] - mna);
            s[nt][1] = __expf(s[nt][1] - mna);
            s[nt][2] = __expf(s[nt][2] - mnb);
            s[nt][3] = __expf(s[nt][3] - mnb);
            suma += s[nt][0] + s[nt][1];
            sumb += s[nt][2] + s[nt][3];
        }
        l_a = l_a * alpha_a + suma;
        l_b = l_b * alpha_b + sumb;

#pragma unroll
        for (int dt = 0; dt < 8; dt++) {
            o[dt][0] *= alpha_a; o[dt][1] *= alpha_a;
            o[dt][2] *= alpha_b; o[dt][3] *= alpha_b;
        }

        // ---- O += P V : P fragments via quad shuffles ----
        const int src1 = (gid << 2) | (l4 >> 1);
        const int src2 = src1 + 2;
        const bool odd = (l4 & 1);
#pragma unroll
        for (int kt = 0; kt < 8; kt++) {
            float e0 = __shfl_sync(0xffffffffu, s[kt][0], src1);
            float e1 = __shfl_sync(0xffffffffu, s[kt][1], src1);
            float e2 = __shfl_sync(0xffffffffu, s[kt][2], src1);
            float e3 = __shfl_sync(0xffffffffu, s[kt][3], src1);
            float f0 = __shfl_sync(0xffffffffu, s[kt][0], src2);
            float f1 = __shfl_sync(0xffffffffu, s[kt][1], src2);
            float f2 = __shfl_sync(0xffffffffu, s[kt][2], src2);
            float f3 = __shfl_sync(0xffffffffu, s[kt][3], src2);
            uint32_t pf[4];
            pf[0] = f2tf(odd ? e1 : e0);   // row gid,   col kt*8+l4
            pf[1] = f2tf(odd ? e3 : e2);   // row gid+8, col kt*8+l4
            pf[2] = f2tf(odd ? f1 : f0);   // row gid,   col kt*8+l4+4
            pf[3] = f2tf(odd ? f3 : f2);   // row gid+8, col kt*8+l4+4
#pragma unroll
            for (int dt = 0; dt < 8; dt++) {
                uint32_t bfr[2];
                const int vb = (kt * 8 + l4) * VPITCH + dt * 8 + gid;
                bfr[0] = Vs[vb];
                bfr[1] = Vs[vb + 4 * VPITCH];
                mma_tf32(o[dt], pf, bfr);
            }
        }

        cp_wait0();
        __syncthreads();
    }

    // ---- finalize ----
    l_a += __shfl_xor_sync(0xffffffffu, l_a, 1);
    l_a += __shfl_xor_sync(0xffffffffu, l_a, 2);
    l_b += __shfl_xor_sync(0xffffffffu, l_b, 1);
    l_b += __shfl_xor_sync(0xffffffffu, l_b, 2);
    const float ia = 1.f / l_a, ib = 1.f / l_b;

    const int b = bh / NHEAD;
    const int h = bh % NHEAD;
    const int sa = qt * 64 + m0 + gid;
    const int sb = sa + 8;
    float* da = ctx + ((size_t)(b * SEQ + sa)) * DMODEL + h * HDIM;
    float* db = ctx + ((size_t)(b * SEQ + sb)) * DMODEL + h * HDIM;
#pragma unroll
    for (int dt = 0; dt < 8; dt++) {
        const int c = dt * 8 + 2 * l4;
        da[c]     = o[dt][0] * ia;
        da[c + 1] = o[dt][1] * ia;
        db[c]     = o[dt][2] * ib;
        db[c + 1] = o[dt][3] * ib;
    }
}

// =================================================================
extern "C" void kernel_launch(void* const* d_in, const int* in_sizes, int n_in,
                              void* d_out, int out_size)
{
    (void)in_sizes; (void)n_in; (void)out_size;
    const float* query = (const float*)d_in[0];
    const float* key   = (const float*)d_in[1];
    const float* value = (const float*)d_in[2];
    const float* Wq = (const float*)d_in[4];
    const float* bq = (const float*)d_in[5];
    const float* Wk = (const float*)d_in[6];
    const float* bk = (const float*)d_in[7];
    const float* Wv = (const float*)d_in[8];
    const float* bv = (const float*)d_in[9];
    const float* Wo = (const float*)d_in[10];
    const float* bo = (const float*)d_in[11];
    float* out = (float*)d_out;

    uint32_t *qp, *kp, *vp; float *cp;
    cudaGetSymbolAddress((void**)&qp, g_q);
    cudaGetSymbolAddress((void**)&kp, g_k);
    cudaGetSymbolAddress((void**)&vp, g_v);
    cudaGetSymbolAddress((void**)&cp, g_ctx);

    static bool init = false;
    if (!init) {
        cudaFuncSetAttribute(attn_tf32, cudaFuncAttributeMaxDynamicSharedMemorySize, ATTN_SMEM);
        init = true;
    }

    // fused QKV projections (z-indexed), tf32 head-split outputs
    GemmArgs qkv;
    qkv.A[0] = query; qkv.A[1] = key; qkv.A[2] = value;
    qkv.W[0] = Wq;    qkv.W[1] = Wk;  qkv.W[2] = Wv;
    qkv.bias[0] = bq; qkv.bias[1] = bk; qkv.bias[2] = bv;
    qkv.out[0] = qp;  qkv.out[1] = kp;  qkv.out[2] = vp;
    qkv.scale[0] = 0.125f; qkv.scale[1] = 1.f; qkv.scale[2] = 1.f;
    qkv.split[0] = 1; qkv.split[1] = 1; qkv.split[2] = 1;
    dim3 gqkv(MROWS / 128, DMODEL / 64, 3);       // (32, 12, 3)
    gemm_fused<<<gqkv, 128>>>(qkv);

    dim3 gattn(SEQ / 64, BHEADS);                 // (32, 24)
    attn_tf32<<<gattn, 128, ATTN_SMEM>>>(qp, kp, vp, cp);

    // output projection (plain float out)
    GemmArgs og;
    og.A[0] = cp; og.W[0] = Wo; og.bias[0] = bo; og.out[0] = out;
    og.scale[0] = 1.f; og.split[0] = 0;
    og.A[1] = og.A[2] = cp; og.W[1] = og.W[2] = Wo; og.bias[1] = og.bias[2] = bo;
    og.out[1] = og.out[2] = out; og.scale[1] = og.scale[2] = 1.f;
    og.split[1] = og.split[2] = 0;
    dim3 gout(MROWS / 128, DMODEL / 64, 1);       // (32, 12)
    gemm_fused<<<gout, 128>>>(og);
}

// round 4
// speedup vs baseline: 4.9429x; 1.3283x over previous
#include <cuda_runtime.h>
#include <cuda_bf16.h>
#include <cstdint>

#define BATCH 2
#define SEQ 2048
#define DMODEL 768
#define NHEAD 12
#define HDIM 64
#define MROWS (BATCH * SEQ)          // 4096
#define BHEADS (BATCH * NHEAD)       // 24

// ---------------- scratch ----------------
__device__ uint32_t g_q[BHEADS * SEQ * HDIM];   // tf32, pre-scaled, [bh][s][d]
__device__ uint32_t g_k[BHEADS * SEQ * HDIM];   // tf32, [bh][s][d]
__device__ uint32_t g_v[BHEADS * SEQ * HDIM];   // tf32, TRANSPOSED [bh][d][s]
__device__ float    g_ctx[MROWS * DMODEL];

__device__ __forceinline__ uint32_t f2tf(float f) {
    uint32_t r; asm("cvt.rna.tf32.f32 %0, %1;" : "=r"(r) : "f"(f)); return r;
}

__device__ __forceinline__ void mma_tf32(float c[4], const uint32_t a[4], const uint32_t b[2]) {
    asm volatile(
        "mma.sync.aligned.m16n8k8.row.col.f32.tf32.tf32.f32 "
        "{%0,%1,%2,%3}, {%4,%5,%6,%7}, {%8,%9}, {%0,%1,%2,%3};"
        : "+f"(c[0]), "+f"(c[1]), "+f"(c[2]), "+f"(c[3])
        : "r"(a[0]), "r"(a[1]), "r"(a[2]), "r"(a[3]), "r"(b[0]), "r"(b[1]));
}

__device__ __forceinline__ void ldsm_x4(uint32_t r[4], uint32_t saddr) {
    asm volatile("ldmatrix.sync.aligned.m8n8.x4.shared.b16 {%0,%1,%2,%3}, [%4];"
        : "=r"(r[0]), "=r"(r[1]), "=r"(r[2]), "=r"(r[3]) : "r"(saddr));
}

__device__ __forceinline__ void cp16(uint32_t s, const void* g) {
    asm volatile("cp.async.cg.shared.global [%0], [%1], 16;" :: "r"(s), "l"(g));
}
__device__ __forceinline__ void cp_commit() { asm volatile("cp.async.commit_group;"); }
__device__ __forceinline__ void cp_wait0()  { asm volatile("cp.async.wait_group 0;"); }

// =================================================================
// Fused GEMM: out[m][n] = A[m][:] . W[n][:] + bias[n]
// CTA tile 128x128, BK=16, 128 threads (4 warps), warp tile 64x64.
// ldmatrix fragment loads. split: 0 plain f32, 1 head-split tf32,
// 2 head-split TRANSPOSED tf32 ([bh][d][s]).
// =================================================================
struct GemmArgs {
    const float* A[3];
    const float* W[3];
    const float* bias[3];
    void*        out[3];
    float        scale[3];
    int          split[3];
};

#define GP 20
__global__ __launch_bounds__(128, 2)
void gemm_fused(GemmArgs args)
{
    __shared__ uint32_t As[2][128 * GP];
    __shared__ uint32_t Bs[2][128 * GP];

    const int z = blockIdx.z;
    const float* __restrict__ A    = args.A[z];
    const float* __restrict__ W    = args.W[z];
    const float* __restrict__ bias = args.bias[z];
    const float scale = args.scale[z];
    const int   split = args.split[z];

    const int tid = threadIdx.x;
    const int w = tid >> 5, lane = tid & 31;
    const int gid = lane >> 2, l4 = lane & 3;
    const int bm = blockIdx.x * 128;
    const int bn = blockIdx.y * 128;
    const int wm = (w & 1) * 64;
    const int wn = (w >> 1) * 64;

    // ldmatrix lane-address components
    const int arow_f = lane & 15;                    // A: row within m16 tile
    const int ahalf  = (lane >> 4) * 4;              // A: k-half
    const int brow_f = ((lane >> 4) << 3) + (lane & 7);  // B: row within n16 pair
    const int bhalf  = ((lane >> 3) & 1) * 4;        // B: k-half

    const uint32_t aSm = (uint32_t)__cvta_generic_to_shared(&As[0][0]);
    const uint32_t bSm = (uint32_t)__cvta_generic_to_shared(&Bs[0][0]);

    // staging: 4 threads per row, 16B each; rows arow + i*32
    const int arow = tid >> 2;
    const int kq4  = (tid & 3) * 4;
    const float* Ag = A + (size_t)(bm + arow) * DMODEL + kq4;
    const float* Wg = W + (size_t)(bn + arow) * DMODEL + kq4;

    float acc[4][8][4];
#pragma unroll
    for (int i = 0; i < 4; i++)
#pragma unroll
        for (int j = 0; j < 8; j++)
#pragma unroll
            for (int t = 0; t < 4; t++) acc[i][j][t] = 0.f;

    float4 ra[4], rb[4];
#define LOADREGS(K0) do { \
    _Pragma("unroll") \
    for (int i = 0; i < 4; i++) { \
        ra[i] = *reinterpret_cast<const float4*>(Ag + (K0) + (size_t)(32 * i) * DMODEL); \
        rb[i] = *reinterpret_cast<const float4*>(Wg + (K0) + (size_t)(32 * i) * DMODEL); \
    } \
} while (0)

#define STORESTAGE(B) do { \
    _Pragma("unroll") \
    for (int i = 0; i < 4; i++) { \
        uint4 u; \
        u.x = f2tf(ra[i].x); u.y = f2tf(ra[i].y); u.z = f2tf(ra[i].z); u.w = f2tf(ra[i].w); \
        *reinterpret_cast<uint4*>(&As[B][(arow + i * 32) * GP + kq4]) = u; \
        u.x = f2tf(rb[i].x); u.y = f2tf(rb[i].y); u.z = f2tf(rb[i].z); u.w = f2tf(rb[i].w); \
        *reinterpret_cast<uint4*>(&Bs[B][(arow + i * 32) * GP + kq4]) = u; \
    } \
} while (0)

    const int nIter = DMODEL / 16;       // 48
    LOADREGS(0);
    STORESTAGE(0);
    LOADREGS(16);
    __syncthreads();

    for (int it = 0; it < nIter; it++) {
        const int buf = it & 1;
        if (it + 1 < nIter) STORESTAGE(buf ^ 1);
        if (it + 2 < nIter) LOADREGS((it + 2) * 16);

        const uint32_t aB = aSm + (uint32_t)(buf * 128 * GP) * 4;
        const uint32_t bB = bSm + (uint32_t)(buf * 128 * GP) * 4;

#pragma unroll
        for (int kk = 0; kk < 16; kk += 8) {
            uint32_t af[4][4], bf[8][2];
#pragma unroll
            for (int mt = 0; mt < 4; mt++)
                ldsm_x4(af[mt], aB + (uint32_t)((wm + mt * 16 + arow_f) * GP + kk + ahalf) * 4);
#pragma unroll
            for (int ntp = 0; ntp < 4; ntp++) {
                uint32_t r[4];
                ldsm_x4(r, bB + (uint32_t)((wn + ntp * 16 + brow_f) * GP + kk + bhalf) * 4);
                bf[2 * ntp][0] = r[0]; bf[2 * ntp][1] = r[1];
                bf[2 * ntp + 1][0] = r[2]; bf[2 * ntp + 1][1] = r[3];
            }
#pragma unroll
            for (int mt = 0; mt < 4; mt++)
#pragma unroll
                for (int nt = 0; nt < 8; nt++)
                    mma_tf32(acc[mt][nt], af[mt], bf[nt]);
        }
        __syncthreads();
    }

    // epilogue
#pragma unroll
    for (int mt = 0; mt < 4; mt++) {
#pragma unroll
        for (int nt = 0; nt < 8; nt++) {
#pragma unroll
            for (int half = 0; half < 2; half++) {
                const int m = bm + wm + mt * 16 + gid + half * 8;
#pragma unroll
                for (int t = 0; t < 2; t++) {
                    const int n = bn + wn + nt * 8 + 2 * l4 + t;
                    float val = (acc[mt][nt][half * 2 + t] + bias[n]) * scale;
                    if (split == 0) {
                        ((float*)args.out[z])[(size_t)m * DMODEL + n] = val;
                    } else {
                        const int b = m >> 11;
                        const int s = m & (SEQ - 1);
                        const int h = n >> 6;
                        const int d = n & (HDIM - 1);
                        uint32_t* o32 = (uint32_t*)args.out[z];
                        if (split == 1)
                            o32[(((size_t)(b * NHEAD + h) * SEQ) + s) * HDIM + d] = f2tf(val);
                        else   // transposed [bh][d][s]
                            o32[(((size_t)(b * NHEAD + h) * HDIM) + d) * SEQ + s] = f2tf(val);
                    }
                }
            }
        }
    }
}

// =================================================================
// Flash attention (causal), tf32, ldmatrix fragments.
// 128 threads (4 warps), q-tile 64. K [bh][s][d], V TRANSPOSED [bh][d][s].
// Double-buffered cp.async staging, 1 barrier per KV tile.
// =================================================================
#define KP 68
#define TW (64 * KP)                          // words per tile buffer: 4352
#define ATTN_SMEM (4 * TW * 4)                // Ks0,Ks1,Vt0,Vt1 = 69632 B

__global__ __launch_bounds__(128, 3)
void attn_tf32(const uint32_t* __restrict__ Q, const uint32_t* __restrict__ K,
               const uint32_t* __restrict__ V, float* __restrict__ ctx)
{
    extern __shared__ uint32_t smu[];
    const uint32_t smem_u32 = (uint32_t)__cvta_generic_to_shared(smu);

    const int tid = threadIdx.x;
    const int w = tid >> 5, lane = tid & 31;
    const int gid = lane >> 2, l4 = lane & 3;
    const int qt = blockIdx.x;
    const int bh = blockIdx.y;
    const int m0 = w * 16;

    const int brow_f = ((lane >> 4) << 3) + (lane & 7);
    const int bhalf  = ((lane >> 3) & 1) * 4;

    const char* Kg = (const char*)(K + ((size_t)bh * SEQ) * HDIM);   // [s][d]
    const char* Vg = (const char*)(V + ((size_t)bh * HDIM) * SEQ);   // [d][s]

    // ---- stage: K tile [n=s][k=d], Vt tile [n=d][k=s] ----
    auto stage = [&](int jt, int buf) {
        const uint32_t ksb = smem_u32 + (uint32_t)(buf * TW) * 4;
        const uint32_t vsb = smem_u32 + (uint32_t)((2 + buf) * TW) * 4;
#pragma unroll
        for (int i = 0; i < 8; i++) {
            const int idx = i * 128 + tid;     // 0..1023
            const int r = idx >> 4;
            const int c4 = (idx & 15) << 2;
            cp16(ksb + (uint32_t)(r * KP + c4) * 4,
                 Kg + ((size_t)(jt * 64 + r) * HDIM + c4) * 4);
            cp16(vsb + (uint32_t)(r * KP + c4) * 4,
                 Vg + ((size_t)r * SEQ + jt * 64 + c4) * 4);
        }
        cp_commit();
    };

    // ---- Q fragments from global (one-time) ----
    uint32_t qf[8][4];
    {
        const uint32_t* Qg = Q + ((size_t)bh * SEQ + qt * 64) * HDIM;
#pragma unroll
        for (int kt = 0; kt < 8; kt++) {
            const int base = (m0 + gid) * HDIM + kt * 8 + l4;
            qf[kt][0] = Qg[base];
            qf[kt][1] = Qg[base + 8 * HDIM];
            qf[kt][2] = Qg[base + 4];
            qf[kt][3] = Qg[base + 8 * HDIM + 4];
        }
    }

    stage(0, 0);
    cp_wait0();
    __syncthreads();

    float o[8][4];
#pragma unroll
    for (int dt = 0; dt < 8; dt++)
#pragma unroll
        for (int t = 0; t < 4; t++) o[dt][t] = 0.f;

    float m_a = -1e30f, m_b = -1e30f;
    float l_a = 0.f, l_b = 0.f;

    const int ntiles = qt + 1;
    for (int jt = 0; jt < ntiles; jt++) {
        const int buf = jt & 1;
        if (jt + 1 < ntiles) stage(jt + 1, buf ^ 1);

        const uint32_t ksB = smem_u32 + (uint32_t)(buf * TW) * 4;
        const uint32_t vtB = smem_u32 + (uint32_t)((2 + buf) * TW) * 4;

        // ---- S = Q K^T ----
        float s[8][4];
#pragma unroll
        for (int nt = 0; nt < 8; nt++)
#pragma unroll
            for (int t = 0; t < 4; t++) s[nt][t] = 0.f;

#pragma unroll
        for (int kt = 0; kt < 8; kt++) {
            uint32_t bf[8][2];
#pragma unroll
            for (int ntp = 0; ntp < 4; ntp++) {
                uint32_t r[4];
                ldsm_x4(r, ksB + (uint32_t)((ntp * 16 + brow_f) * KP + kt * 8 + bhalf) * 4);
                bf[2 * ntp][0] = r[0]; bf[2 * ntp][1] = r[1];
                bf[2 * ntp + 1][0] = r[2]; bf[2 * ntp + 1][1] = r[3];
            }
#pragma unroll
            for (int nt = 0; nt < 8; nt++)
                mma_tf32(s[nt], qf[kt], bf[nt]);
        }

        // ---- causal mask on diagonal tile ----
        if (jt == qt) {
            const int ra = m0 + gid, rb = ra + 8;
#pragma unroll
            for (int nt = 0; nt < 8; nt++) {
                const int c = nt * 8 + 2 * l4;
                if (c > ra)     s[nt][0] = -1e30f;
                if (c + 1 > ra) s[nt][1] = -1e30f;
                if (c > rb)     s[nt][2] = -1e30f;
                if (c + 1 > rb) s[nt][3] = -1e30f;
            }
        }

        // ---- online softmax ----
        float mxa = -1e30f, mxb = -1e30f;
#pragma unroll
        for (int nt = 0; nt < 8; nt++) {
            mxa = fmaxf(mxa, fmaxf(s[nt][0], s[nt][1]));
            mxb = fmaxf(mxb, fmaxf(s[nt][2], s[nt][3]));
        }
        mxa = fmaxf(mxa, __shfl_xor_sync(0xffffffffu, mxa, 1));
        mxa = fmaxf(mxa, __shfl_xor_sync(0xffffffffu, mxa, 2));
        mxb = fmaxf(mxb, __shfl_xor_sync(0xffffffffu, mxb, 1));
        mxb = fmaxf(mxb, __shfl_xor_sync(0xffffffffu, mxb, 2));

        const float mna = fmaxf(m_a, mxa);
        const float mnb = fmaxf(m_b, mxb);
        const float alpha_a = __expf(m_a - mna);
        const float alpha_b = __expf(m_b - mnb);
        m_a = mna; m_b = mnb;

        float suma = 0.f, sumb = 0.f;
#pragma unroll
        for (int nt = 0; nt < 8; nt++) {
            s[nt][0] = __expf(s[nt][0] - mna);
            s[nt][1] = __expf(s[nt][1] - mna);
            s[nt][2] = __expf(s[nt][2] - mnb);
            s[nt][3] = __expf(s[nt][3] - mnb);
            suma += s[nt][0] + s[nt][1];
            sumb += s[nt][2] + s[nt][3];
        }
        l_a = l_a * alpha_a + suma;
        l_b = l_b * alpha_b + sumb;

#pragma unroll
        for (int dt = 0; dt < 8; dt++) {
            o[dt][0] *= alpha_a; o[dt][1] *= alpha_a;
            o[dt][2] *= alpha_b; o[dt][3] *= alpha_b;
        }

        // ---- O += P V ----
        const int src1 = (gid << 2) | (l4 >> 1);
        const int src2 = src1 + 2;
        const bool odd = (l4 & 1);
#pragma unroll
        for (int kt = 0; kt < 8; kt++) {
            float e0 = __shfl_sync(0xffffffffu, s[kt][0], src1);
            float e1 = __shfl_sync(0xffffffffu, s[kt][1], src1);
            float e2 = __shfl_sync(0xffffffffu, s[kt][2], src1);
            float e3 = __shfl_sync(0xffffffffu, s[kt][3], src1);
            float f0 = __shfl_sync(0xffffffffu, s[kt][0], src2);
            float f1 = __shfl_sync(0xffffffffu, s[kt][1], src2);
            float f2 = __shfl_sync(0xffffffffu, s[kt][2], src2);
            float f3 = __shfl_sync(0xffffffffu, s[kt][3], src2);
            uint32_t pf[4];
            pf[0] = f2tf(odd ? e1 : e0);
            pf[1] = f2tf(odd ? e3 : e2);
            pf[2] = f2tf(odd ? f1 : f0);
            pf[3] = f2tf(odd ? f3 : f2);

            uint32_t bv[8][2];
#pragma unroll
            for (int dtp = 0; dtp < 4; dtp++) {
                uint32_t r[4];
                ldsm_x4(r, vtB + (uint32_t)((dtp * 16 + brow_f) * KP + kt * 8 + bhalf) * 4);
                bv[2 * dtp][0] = r[0]; bv[2 * dtp][1] = r[1];
                bv[2 * dtp + 1][0] = r[2]; bv[2 * dtp + 1][1] = r[3];
            }
#pragma unroll
            for (int dt = 0; dt < 8; dt++)
                mma_tf32(o[dt], pf, bv[dt]);
        }

        cp_wait0();
        __syncthreads();
    }

    // ---- finalize ----
    l_a += __shfl_xor_sync(0xffffffffu, l_a, 1);
    l_a += __shfl_xor_sync(0xffffffffu, l_a, 2);
    l_b += __shfl_xor_sync(0xffffffffu, l_b, 1);
    l_b += __shfl_xor_sync(0xffffffffu, l_b, 2);
    const float ia = 1.f / l_a, ib = 1.f / l_b;

    const int b = bh / NHEAD;
    const int h = bh % NHEAD;
    const int sa = qt * 64 + m0 + gid;
    const int sb = sa + 8;
    float* da = ctx + ((size_t)(b * SEQ + sa)) * DMODEL + h * HDIM;
    float* db = ctx + ((size_t)(b * SEQ + sb)) * DMODEL + h * HDIM;
#pragma unroll
    for (int dt = 0; dt < 8; dt++) {
        const int c = dt * 8 + 2 * l4;
        da[c]     = o[dt][0] * ia;
        da[c + 1] = o[dt][1] * ia;
        db[c]     = o[dt][2] * ib;
        db[c + 1] = o[dt][3] * ib;
    }
}

// =================================================================
extern "C" void kernel_launch(void* const* d_in, const int* in_sizes, int n_in,
                              void* d_out, int out_size)
{
    (void)in_sizes; (void)n_in; (void)out_size;
    const float* query = (const float*)d_in[0];
    const float* key   = (const float*)d_in[1];
    const float* value = (const float*)d_in[2];
    const float* Wq = (const float*)d_in[4];
    const float* bq = (const float*)d_in[5];
    const float* Wk = (const float*)d_in[6];
    const float* bk = (const float*)d_in[7];
    const float* Wv = (const float*)d_in[8];
    const float* bv = (const float*)d_in[9];
    const float* Wo = (const float*)d_in[10];
    const float* bo = (const float*)d_in[11];
    float* out = (float*)d_out;

    uint32_t *qp, *kp, *vp; float *cp;
    cudaGetSymbolAddress((void**)&qp, g_q);
    cudaGetSymbolAddress((void**)&kp, g_k);
    cudaGetSymbolAddress((void**)&vp, g_v);
    cudaGetSymbolAddress((void**)&cp, g_ctx);

    static bool init = false;
    if (!init) {
        cudaFuncSetAttribute(attn_tf32, cudaFuncAttributeMaxDynamicSharedMemorySize, ATTN_SMEM);
        init = true;
    }

    // fused QKV projections
    GemmArgs qkv;
    qkv.A[0] = query; qkv.A[1] = key; qkv.A[2] = value;
    qkv.W[0] = Wq;    qkv.W[1] = Wk;  qkv.W[2] = Wv;
    qkv.bias[0] = bq; qkv.bias[1] = bk; qkv.bias[2] = bv;
    qkv.out[0] = qp;  qkv.out[1] = kp;  qkv.out[2] = vp;
    qkv.scale[0] = 0.125f; qkv.scale[1] = 1.f; qkv.scale[2] = 1.f;
    qkv.split[0] = 1; qkv.split[1] = 1; qkv.split[2] = 2;   // V transposed
    dim3 gqkv(MROWS / 128, DMODEL / 128, 3);      // (32, 6, 3)
    gemm_fused<<<gqkv, 128>>>(qkv);

    dim3 gattn(SEQ / 64, BHEADS);                 // (32, 24)
    attn_tf32<<<gattn, 128, ATTN_SMEM>>>(qp, kp, vp, cp);

    // output projection
    GemmArgs og;
    og.A[0] = cp; og.W[0] = Wo; og.bias[0] = bo; og.out[0] = out;
    og.scale[0] = 1.f; og.split[0] = 0;
    og.A[1] = og.A[2] = cp; og.W[1] = og.W[2] = Wo; og.bias[1] = og.bias[2] = bo;
    og.out[1] = og.out[2] = out; og.scale[1] = og.scale[2] = 1.f;
    og.split[1] = og.split[2] = 0;
    dim3 gout(MROWS / 128, DMODEL / 128, 1);      // (32, 6)
    gemm_fused<<<gout, 128>>>(og);
}